// round 15
// baseline (speedup 1.0000x reference)
#include <cuda_runtime.h>
#include <cuda_fp16.h>
#include <math.h>
#include <stdint.h>

#define HIDDEN 3072
#define NH     32
#define HD     96
#define OPSZ   9216   // 32*96 + 2*32*96
#define BB     2
#define LL     2048
#define MTOK   4096   // BB*LL

// ---------------- scratch (static device globals; no allocation) ----------------
__device__ float  g_qkv[(size_t)MTOK * OPSZ];      // [token, 9216] fp32: q | k | v
__device__ __half g_attnh[(size_t)MTOK * HIDDEN];  // fp16 attention output
__device__ __half g_xh [(size_t)MTOK * HIDDEN];    // fp16 x
__device__ __half g_wqh[(size_t)OPSZ * HIDDEN];    // fp16 Wqkv
__device__ __half g_woh[(size_t)HIDDEN * HIDDEN];  // fp16 Wo
__device__ __half g_qh [(size_t)MTOK * HIDDEN];    // head-major fp16 Q (scaled, roped)
__device__ __half g_kh [(size_t)MTOK * HIDDEN];    // head-major fp16 K (roped)
__device__ __half g_vh [(size_t)MTOK * HIDDEN];    // head-major fp16 V
__device__ float  g_cos[LL * 48];
__device__ float  g_sin[LL * 48];

// ---------------- fp32 -> fp16 convert ----------------
__global__ void to_half_kernel(const float* __restrict__ in,
                               __half* __restrict__ outp, int n4) {
    int i = blockIdx.x * blockDim.x + threadIdx.x;
    if (i >= n4) return;
    float4 v = ((const float4*)in)[i];
    __half2 h0 = __floats2half2_rn(v.x, v.y);
    __half2 h1 = __floats2half2_rn(v.z, v.w);
    uint2 o;
    o.x = *(uint32_t*)&h0;
    o.y = *(uint32_t*)&h1;
    ((uint2*)outp)[i] = o;
}

// ---------------- RoPE table (double precision phases) ----------------
__global__ void rope_table_kernel() {
    int idx = blockIdx.x * blockDim.x + threadIdx.x;
    if (idx >= LL * 48) return;
    int i = idx % 48;
    int l = idx / 48;
    double invf = exp(-(double)i / 48.0 * log(10000.0));
    double ang  = (double)l * invf;
    double S    = sqrt(17.0 / 12.0);   // sqrt(1 + ln32/ln4096)
    double s, c;
    sincos(ang, &s, &c);
    g_cos[idx] = (float)(c * S);
    g_sin[idx] = (float)(s * S);
}

// ---------------- RoPE + head-major fp16 conversion of q,k,v ----------------
__global__ void rope_conv_kernel() {
    int idx = blockIdx.x * blockDim.x + threadIdx.x;
    const int total = MTOK * NH * 48;
    if (idx >= total) return;
    int i = idx % 48;
    int h = (idx / 48) % NH;
    int t = idx / (48 * NH);
    int b = t >> 11;
    int l = t & (LL - 1);
    float c = g_cos[l * 48 + i];
    float s = g_sin[l * 48 + i];
    const float scale = 0.10206207261596577f;  // 96^-0.5

    const float* qb = g_qkv + (size_t)t * OPSZ + h * HD;
    const float* kb = qb + 3072;
    const float* vb = qb + 6144;

    size_t obase = ((size_t)(b * NH + h) * LL + l) * HD;

    float q0 = qb[i], q1 = qb[i + 48];
    g_qh[obase + i]      = __float2half_rn((q0 * c - q1 * s) * scale);
    g_qh[obase + i + 48] = __float2half_rn((q1 * c + q0 * s) * scale);

    float k0 = kb[i], k1 = kb[i + 48];
    g_kh[obase + i]      = __float2half_rn(k0 * c - k1 * s);
    g_kh[obase + i + 48] = __float2half_rn(k1 * c + k0 * s);

    g_vh[obase + i]      = __float2half_rn(vb[i]);
    g_vh[obase + i + 48] = __float2half_rn(vb[i + 48]);
}

// ---------------- common MMA helpers ----------------
__device__ __forceinline__ void cp16(uint32_t dst, const void* src) {
    asm volatile("cp.async.cg.shared.global [%0], [%1], 16;\n" :: "r"(dst), "l"(src));
}

__device__ __forceinline__ void ldsm4(uint32_t& r0, uint32_t& r1,
                                      uint32_t& r2, uint32_t& r3, uint32_t addr) {
    asm volatile("ldmatrix.sync.aligned.m8n8.x4.shared.b16 {%0,%1,%2,%3}, [%4];"
                 : "=r"(r0), "=r"(r1), "=r"(r2), "=r"(r3) : "r"(addr));
}

__device__ __forceinline__ void ldsm4t(uint32_t& r0, uint32_t& r1,
                                       uint32_t& r2, uint32_t& r3, uint32_t addr) {
    asm volatile("ldmatrix.sync.aligned.m8n8.x4.trans.shared.b16 {%0,%1,%2,%3}, [%4];"
                 : "=r"(r0), "=r"(r1), "=r"(r2), "=r"(r3) : "r"(addr));
}

__device__ __forceinline__ void mma_f16(
    float& d0, float& d1, float& d2, float& d3,
    uint32_t a0, uint32_t a1, uint32_t a2, uint32_t a3,
    uint32_t b0, uint32_t b1)
{
    asm volatile(
        "mma.sync.aligned.m16n8k16.row.col.f32.f16.f16.f32 "
        "{%0,%1,%2,%3}, {%4,%5,%6,%7}, {%8,%9}, {%0,%1,%2,%3};"
        : "+f"(d0), "+f"(d1), "+f"(d2), "+f"(d3)
        : "r"(a0), "r"(a1), "r"(a2), "r"(a3), "r"(b0), "r"(b1));
}

__device__ __forceinline__ uint32_t packh2(float a, float b) {
    __half2 h = __floats2half2_rn(a, b);
    return *(uint32_t*)&h;
}

// ============ fp16 tensor-core GEMM: C[M,N] = A[M,K] * B[N,K]^T (fp32 accum) ============
// BM=128, BN=128, BK=32. 128 threads = 4 warps in 2(M) x 2(N); warp tile 64x64
// (same 8-LDSM / 32-HMMA ratio as the BN=256 config).
// __launch_bounds__(128, 3): 3 CTAs/SM -> 12 warps/SM (3 per SMSP) for latency hiding.
// 2-stage cp.async pipeline, one __syncthreads per 32-k iteration.
#define HPITCH 40
#define ASTG_B (128 * HPITCH * 2)          // 10240 B
#define BSTG_B (128 * HPITCH * 2)          // 10240 B
#define GEMM_SMEM_BYTES (2 * (ASTG_B + BSTG_B))  // 40960 B

__global__ __launch_bounds__(128, 3) void gemm_f16_nt_kernel(
    const __half* __restrict__ A, const __half* __restrict__ Bm,
    float* __restrict__ C, int M, int N, int K)
{
    extern __shared__ __align__(16) char smc[];
    const uint32_t smem_u32 = (uint32_t)__cvta_generic_to_shared(smc);
    const uint32_t sAbase = smem_u32;                 // [2][ASTG_B]
    const uint32_t sBbase = smem_u32 + 2 * ASTG_B;    // [2][BSTG_B]

    const int tid  = threadIdx.x;
    const int w    = tid >> 5;         // 0..3
    const int lane = tid & 31;
    const int wm   = w >> 1;           // 0..1  (M offset 64)
    const int wn   = w & 1;            // 0..1  (N offset 64)
    const int g    = lane >> 2;
    const int tk   = lane & 3;
    const int bm   = blockIdx.y * 128;
    const int bn   = blockIdx.x * 128;

    const int aRow = lane & 15;
    const int aK   = (lane >> 4) << 3;
    const int bRow = (lane & 7) + ((lane >> 4) << 3);
    const int bK   = lane & 8;

    // loader: thread t handles full 32-half k-row t of A and of B (4 x 16B each)
    const __half* ApA = A  + (size_t)(bm + tid) * K;
    const __half* BpB = Bm + (size_t)(bn + tid) * K;

    const uint32_t dstA0 = sAbase + (uint32_t)(tid * 80);
    const uint32_t dstB0 = sBbase + (uint32_t)(tid * 80);

    float acc[4][8][4];
#pragma unroll
    for (int mi = 0; mi < 4; mi++)
#pragma unroll
        for (int ni = 0; ni < 8; ni++)
#pragma unroll
            for (int r = 0; r < 4; r++) acc[mi][ni][r] = 0.0f;

    {
#pragma unroll
        for (int j = 0; j < 4; j++) {
            cp16(dstA0 + j * 16u, ApA + j * 8);
            cp16(dstB0 + j * 16u, BpB + j * 8);
        }
        asm volatile("cp.async.commit_group;\n" ::: "memory");
    }

    int s = 0;
    for (int kb = 0; kb < K; kb += 32) {
        asm volatile("cp.async.wait_group 0;\n" ::: "memory");
        __syncthreads();

        if (kb + 32 < K) {
            const uint32_t so = (uint32_t)(s ^ 1);
            const uint32_t dA = dstA0 + so * ASTG_B;
            const uint32_t dB = dstB0 + so * BSTG_B;
            const __half* a0 = ApA + kb + 32;
            const __half* b0 = BpB + kb + 32;
#pragma unroll
            for (int j = 0; j < 4; j++) {
                cp16(dA + j * 16u, a0 + j * 8);
                cp16(dB + j * 16u, b0 + j * 8);
            }
            asm volatile("cp.async.commit_group;\n" ::: "memory");
        }

        const uint32_t Ac = sAbase + (uint32_t)s * ASTG_B;
        const uint32_t Bc = sBbase + (uint32_t)s * BSTG_B;

#pragma unroll
        for (int ks = 0; ks < 2; ks++) {
            const int k0 = ks * 16;
            uint32_t af[4][4];
            uint32_t bf[4][4];
#pragma unroll
            for (int mi = 0; mi < 4; mi++) {
                int row = wm * 64 + mi * 16 + aRow;
                ldsm4(af[mi][0], af[mi][1], af[mi][2], af[mi][3],
                      Ac + (uint32_t)((row * HPITCH + k0 + aK) * 2));
            }
#pragma unroll
            for (int n2 = 0; n2 < 4; n2++) {
                int row = wn * 64 + n2 * 16 + bRow;
                ldsm4(bf[n2][0], bf[n2][1], bf[n2][2], bf[n2][3],
                      Bc + (uint32_t)((row * HPITCH + k0 + bK) * 2));
            }
#pragma unroll
            for (int mi = 0; mi < 4; mi++)
#pragma unroll
                for (int n2 = 0; n2 < 4; n2++) {
                    mma_f16(acc[mi][2 * n2][0], acc[mi][2 * n2][1],
                            acc[mi][2 * n2][2], acc[mi][2 * n2][3],
                            af[mi][0], af[mi][1], af[mi][2], af[mi][3],
                            bf[n2][0], bf[n2][1]);
                    mma_f16(acc[mi][2 * n2 + 1][0], acc[mi][2 * n2 + 1][1],
                            acc[mi][2 * n2 + 1][2], acc[mi][2 * n2 + 1][3],
                            af[mi][0], af[mi][1], af[mi][2], af[mi][3],
                            bf[n2][2], bf[n2][3]);
                }
        }
        s ^= 1;
    }

    // epilogue: c0:(g,2tk) c1:(g,2tk+1) c2:(g+8,2tk) c3:(g+8,2tk+1)
#pragma unroll
    for (int mi = 0; mi < 4; mi++) {
#pragma unroll
        for (int ni = 0; ni < 8; ni++) {
            int row = bm + wm * 64 + mi * 16 + g;
            int col = bn + wn * 64 + ni * 8 + tk * 2;
            *(float2*)(C + (size_t)row * N + col) =
                make_float2(acc[mi][ni][0], acc[mi][ni][1]);
            *(float2*)(C + (size_t)(row + 8) * N + col) =
                make_float2(acc[mi][ni][2], acc[mi][ni][3]);
        }
    }
}

// ============ fp16 tensor-core flash attention (3-stage KV ring) ============
#define VP 104
#define QS_BYTES (128 * VP * 2)
#define KV_BYTES (64 * VP * 2)
#define KVSTG    (2 * KV_BYTES)
#define FLASH2_SMEM (QS_BYTES + 3 * KVSTG)  // 106496

__global__ __launch_bounds__(256) void flash_mma_kernel(
    const __half* __restrict__ qh, const __half* __restrict__ kh,
    const __half* __restrict__ vh, __half* __restrict__ out)
{
    extern __shared__ __align__(16) char smc[];
    const uint32_t sb = (uint32_t)__cvta_generic_to_shared(smc);

    const int tid  = threadIdx.x;
    const int w    = tid >> 5;
    const int lane = tid & 31;
    const int qt   = (int)gridDim.x - 1 - (int)blockIdx.x;  // heavy tiles first
    const int bh   = blockIdx.y;
    const int b    = bh >> 5;

    const __half* qbase = qh + ((size_t)bh * LL + qt * 128) * HD;
    const __half* kbase = kh + (size_t)bh * LL * HD;
    const __half* vbase = vh + (size_t)bh * LL * HD;

    const int a15 = lane & 15;
    const int a8  = (lane >> 4) << 3;
    const int bRw = (lane & 7) + ((lane >> 4) << 3);
    const int bK8 = lane & 8;
    const int g   = lane >> 2;
    const int tk  = lane & 3;

    const int qrow = tid >> 1;
    const int qoff = (tid & 1) * 48;
    const int kvrow = (tid & 127) >> 1;
    const int kvoff = (tid & 1) * 48;
    const int isV   = tid >> 7;

    const uint32_t qdst = sb + (uint32_t)((qrow * VP + qoff) * 2);
    const __half* qsrc = qbase + qrow * HD + qoff;

    const int nkb = 2 * qt + 2;

    // prologue: group0 = Q + KV0 (stage 0); group1 = KV1 (stage 1)
#pragma unroll
    for (int j = 0; j < 6; j++)
        cp16(qdst + j * 16u, qsrc + j * 8);
    {
        const uint32_t kvd = sb + QS_BYTES + (uint32_t)(isV * KV_BYTES)
                           + (uint32_t)((kvrow * VP + kvoff) * 2);
        const __half* src = (isV ? vbase : kbase) + (size_t)kvrow * HD + kvoff;
#pragma unroll
        for (int j = 0; j < 6; j++)
            cp16(kvd + j * 16u, src + j * 8);
        asm volatile("cp.async.commit_group;\n" ::: "memory");
    }
    {
        const uint32_t kvd = sb + QS_BYTES + KVSTG + (uint32_t)(isV * KV_BYTES)
                           + (uint32_t)((kvrow * VP + kvoff) * 2);
        const __half* src = (isV ? vbase : kbase) + (size_t)(64 + kvrow) * HD + kvoff;
#pragma unroll
        for (int j = 0; j < 6; j++)
            cp16(kvd + j * 16u, src + j * 8);
        asm volatile("cp.async.commit_group;\n" ::: "memory");
    }

    float of[12][4];
#pragma unroll
    for (int n = 0; n < 12; n++)
#pragma unroll
        for (int r = 0; r < 4; r++) of[n][r] = 0.0f;
    float m0 = -INFINITY, m1 = -INFINITY, l0 = 0.0f, l1 = 0.0f;
    uint32_t qf[6][4];

    for (int kb = 0; kb < nkb; kb++) {
        if (kb < nkb - 1) asm volatile("cp.async.wait_group 1;\n" ::: "memory");
        else              asm volatile("cp.async.wait_group 0;\n" ::: "memory");
        __syncthreads();

        if (kb + 2 < nkb) {
            const uint32_t st = (uint32_t)((kb + 2) % 3);
            const uint32_t kvd = sb + QS_BYTES + st * KVSTG + (uint32_t)(isV * KV_BYTES)
                               + (uint32_t)((kvrow * VP + kvoff) * 2);
            const __half* src = (isV ? vbase : kbase)
                              + (size_t)((kb + 2) * 64 + kvrow) * HD + kvoff;
#pragma unroll
            for (int j = 0; j < 6; j++)
                cp16(kvd + j * 16u, src + j * 8);
            asm volatile("cp.async.commit_group;\n" ::: "memory");
        }

        if (kb == 0) {
#pragma unroll
            for (int kc = 0; kc < 6; kc++)
                ldsm4(qf[kc][0], qf[kc][1], qf[kc][2], qf[kc][3],
                      sb + (uint32_t)(((w * 16 + a15) * VP + kc * 16 + a8) * 2));
        }

        const uint32_t Kc = sb + QS_BYTES + (uint32_t)(kb % 3) * KVSTG;
        const uint32_t Vc = Kc + KV_BYTES;

        float sf[8][4];
#pragma unroll
        for (int n = 0; n < 8; n++)
#pragma unroll
            for (int r = 0; r < 4; r++) sf[n][r] = 0.0f;

#pragma unroll
        for (int kc = 0; kc < 6; kc++) {
            uint32_t kf[4][4];
#pragma unroll
            for (int n2 = 0; n2 < 4; n2++)
                ldsm4(kf[n2][0], kf[n2][1], kf[n2][2], kf[n2][3],
                      Kc + (uint32_t)(((n2 * 16 + bRw) * VP + kc * 16 + bK8) * 2));
#pragma unroll
            for (int n2 = 0; n2 < 4; n2++) {
                mma_f16(sf[2 * n2][0], sf[2 * n2][1], sf[2 * n2][2], sf[2 * n2][3],
                        qf[kc][0], qf[kc][1], qf[kc][2], qf[kc][3],
                        kf[n2][0], kf[n2][1]);
                mma_f16(sf[2 * n2 + 1][0], sf[2 * n2 + 1][1],
                        sf[2 * n2 + 1][2], sf[2 * n2 + 1][3],
                        qf[kc][0], qf[kc][1], qf[kc][2], qf[kc][3],
                        kf[n2][2], kf[n2][3]);
            }
        }

        if (kb * 64 + 63 > qt * 128 + w * 16) {
            const int r0 = qt * 128 + w * 16 + g;
            const int cb = kb * 64 + tk * 2;
#pragma unroll
            for (int n = 0; n < 8; n++) {
                int c = cb + n * 8;
                if (c     > r0)     sf[n][0] = -1e30f;
                if (c + 1 > r0)     sf[n][1] = -1e30f;
                if (c     > r0 + 8) sf[n][2] = -1e30f;
                if (c + 1 > r0 + 8) sf[n][3] = -1e30f;
            }
        }

        float mx0 = -1e30f, mx1 = -1e30f;
#pragma unroll
        for (int n = 0; n < 8; n++) {
            mx0 = fmaxf(mx0, fmaxf(sf[n][0], sf[n][1]));
            mx1 = fmaxf(mx1, fmaxf(sf[n][2], sf[n][3]));
        }
        mx0 = fmaxf(mx0, __shfl_xor_sync(0xffffffffu, mx0, 1));
        mx0 = fmaxf(mx0, __shfl_xor_sync(0xffffffffu, mx0, 2));
        mx1 = fmaxf(mx1, __shfl_xor_sync(0xffffffffu, mx1, 1));
        mx1 = fmaxf(mx1, __shfl_xor_sync(0xffffffffu, mx1, 2));

        float mn0 = fmaxf(m0, mx0), mn1 = fmaxf(m1, mx1);
        float al0 = __expf(m0 - mn0), al1 = __expf(m1 - mn1);

        uint32_t pf[8][2];
        float ps0 = 0.0f, ps1 = 0.0f;
#pragma unroll
        for (int n = 0; n < 8; n++) {
            float p0 = __expf(sf[n][0] - mn0);
            float p1 = __expf(sf[n][1] - mn0);
            float p2 = __expf(sf[n][2] - mn1);
            float p3 = __expf(sf[n][3] - mn1);
            ps0 += p0 + p1;
            ps1 += p2 + p3;
            pf[n][0] = packh2(p0, p1);
            pf[n][1] = packh2(p2, p3);
        }
        ps0 += __shfl_xor_sync(0xffffffffu, ps0, 1);
        ps0 += __shfl_xor_sync(0xffffffffu, ps0, 2);
        ps1 += __shfl_xor_sync(0xffffffffu, ps1, 1);
        ps1 += __shfl_xor_sync(0xffffffffu, ps1, 2);

        l0 = l0 * al0 + ps0;
        l1 = l1 * al1 + ps1;
        m0 = mn0;
        m1 = mn1;
#pragma unroll
        for (int n = 0; n < 12; n++) {
            of[n][0] *= al0; of[n][1] *= al0;
            of[n][2] *= al1; of[n][3] *= al1;
        }

#pragma unroll
        for (int kk = 0; kk < 4; kk++) {
            uint32_t a0 = pf[2 * kk][0],     a1 = pf[2 * kk][1];
            uint32_t a2 = pf[2 * kk + 1][0], a3 = pf[2 * kk + 1][1];
#pragma unroll
            for (int nv = 0; nv < 6; nv++) {
                uint32_t vf0, vf1, vf2, vf3;
                ldsm4t(vf0, vf1, vf2, vf3,
                       Vc + (uint32_t)(((kk * 16 + a15) * VP + nv * 16 + a8) * 2));
                mma_f16(of[2 * nv][0], of[2 * nv][1], of[2 * nv][2], of[2 * nv][3],
                        a0, a1, a2, a3, vf0, vf1);
                mma_f16(of[2 * nv + 1][0], of[2 * nv + 1][1],
                        of[2 * nv + 1][2], of[2 * nv + 1][3],
                        a0, a1, a2, a3, vf2, vf3);
            }
        }
    }

    const float inv0 = 1.0f / l0;
    const float inv1 = 1.0f / l1;
    const int row0 = qt * 128 + w * 16 + g;
    const int h    = bh & 31;
#pragma unroll
    for (int n = 0; n < 12; n++) {
        int col = h * HD + n * 8 + tk * 2;
        __half2 o0 = __floats2half2_rn(of[n][0] * inv0, of[n][1] * inv0);
        __half2 o1 = __floats2half2_rn(of[n][2] * inv1, of[n][3] * inv1);
        *(__half2*)(out + (size_t)(b * LL + row0) * HIDDEN + col) = o0;
        *(__half2*)(out + (size_t)(b * LL + row0 + 8) * HIDDEN + col) = o1;
    }
}

// ---------------- launch ----------------
extern "C" void kernel_launch(void* const* d_in, const int* in_sizes, int n_in,
                              void* d_out, int out_size)
{
    const float* x    = (const float*)d_in[0];
    const float* Wqkv = (const float*)d_in[1];
    const float* Wo   = (const float*)d_in[2];
    float* out = (float*)d_out;

    float*  qkv;   cudaGetSymbolAddress((void**)&qkv,   g_qkv);
    __half* attnh; cudaGetSymbolAddress((void**)&attnh, g_attnh);
    __half* xh;    cudaGetSymbolAddress((void**)&xh,    g_xh);
    __half* wqh;   cudaGetSymbolAddress((void**)&wqh,   g_wqh);
    __half* woh;   cudaGetSymbolAddress((void**)&woh,   g_woh);
    __half* qh;    cudaGetSymbolAddress((void**)&qh,    g_qh);
    __half* kh;    cudaGetSymbolAddress((void**)&kh,    g_kh);
    __half* vh;    cudaGetSymbolAddress((void**)&vh,    g_vh);

    cudaFuncSetAttribute(gemm_f16_nt_kernel,
                         cudaFuncAttributeMaxDynamicSharedMemorySize, GEMM_SMEM_BYTES);
    cudaFuncSetAttribute(flash_mma_kernel,
                         cudaFuncAttributeMaxDynamicSharedMemorySize, FLASH2_SMEM);

    // 0) fp16 conversion of GEMM inputs
    {
        int n4x = MTOK * HIDDEN / 4;
        to_half_kernel<<<(n4x + 255) / 256, 256>>>(x, xh, n4x);
        int n4q = OPSZ * HIDDEN / 4;
        to_half_kernel<<<(n4q + 255) / 256, 256>>>(Wqkv, wqh, n4q);
        int n4o = HIDDEN * HIDDEN / 4;
        to_half_kernel<<<(n4o + 255) / 256, 256>>>(Wo, woh, n4o);
    }
    // 1) QKV = x @ Wqkv^T : [4096, 9216]  (fp16 MMA, fp32 accum, 3 CTAs/SM)
    {
        dim3 grid(OPSZ / 128, MTOK / 128);
        gemm_f16_nt_kernel<<<grid, 128, GEMM_SMEM_BYTES>>>(xh, wqh, qkv, MTOK, OPSZ, HIDDEN);
    }
    // 2) RoPE table + rope/convert to head-major fp16 q,k,v
    {
        int n1 = LL * 48;
        rope_table_kernel<<<(n1 + 255) / 256, 256>>>();
        int n2 = MTOK * NH * 48;
        rope_conv_kernel<<<(n2 + 255) / 256, 256>>>();
    }
    // 3) tensor-core flash attention -> attnh [4096, 3072] fp16 (3-stage ring)
    {
        dim3 grid(LL / 128, BB * NH);
        flash_mma_kernel<<<grid, 256, FLASH2_SMEM>>>(qh, kh, vh, attnh);
    }
    // 4) out = attn @ Wo^T : [4096, 3072]  (fp16 MMA, fp32 accum, 3 CTAs/SM)
    {
        dim3 grid(HIDDEN / 128, MTOK / 128);
        gemm_f16_nt_kernel<<<grid, 128, GEMM_SMEM_BYTES>>>(attnh, woh, out, MTOK, HIDDEN, HIDDEN);
    }
}

// round 16
// speedup vs baseline: 1.0280x; 1.0280x over previous
#include <cuda_runtime.h>
#include <cuda_fp16.h>
#include <math.h>
#include <stdint.h>

#define HIDDEN 3072
#define NH     32
#define HD     96
#define OPSZ   9216   // 32*96 + 2*32*96
#define BB     2
#define LL     2048
#define MTOK   4096   // BB*LL

// ---------------- scratch (static device globals; no allocation) ----------------
__device__ float  g_qkv[(size_t)MTOK * OPSZ];      // [token, 9216] fp32: q | k | v
__device__ __half g_attnh[(size_t)MTOK * HIDDEN];  // fp16 attention output
__device__ __half g_xh [(size_t)MTOK * HIDDEN];    // fp16 x
__device__ __half g_wqh[(size_t)OPSZ * HIDDEN];    // fp16 Wqkv
__device__ __half g_woh[(size_t)HIDDEN * HIDDEN];  // fp16 Wo
__device__ __half g_qh [(size_t)MTOK * HIDDEN];    // head-major fp16 Q (scaled, roped)
__device__ __half g_kh [(size_t)MTOK * HIDDEN];    // head-major fp16 K (roped)
__device__ __half g_vh [(size_t)MTOK * HIDDEN];    // head-major fp16 V
__device__ float  g_cos[LL * 48];
__device__ float  g_sin[LL * 48];
__device__ double g_cA[32 * 48], g_sA[32 * 48];    // coarse phases (l = 64a)
__device__ double g_cB[64 * 48], g_sB[64 * 48];    // fine phases   (l = r)

// ---------------- fused fp32 -> fp16 convert of x, Wqkv, Wo ----------------
#define N4X (MTOK * HIDDEN / 4)
#define N4Q (OPSZ * HIDDEN / 4)
#define N4O (HIDDEN * HIDDEN / 4)

__global__ void to_half_fused_kernel(const float* __restrict__ x,
                                     const float* __restrict__ wq,
                                     const float* __restrict__ wo) {
    int i = blockIdx.x * blockDim.x + threadIdx.x;
    const float* src;
    __half* dst;
    int j;
    if (i < N4X)            { src = x;  dst = g_xh;  j = i; }
    else if (i < N4X + N4Q) { src = wq; dst = g_wqh; j = i - N4X; }
    else if (i < N4X + N4Q + N4O) { src = wo; dst = g_woh; j = i - N4X - N4Q; }
    else return;
    float4 v = ((const float4*)src)[j];
    __half2 h0 = __floats2half2_rn(v.x, v.y);
    __half2 h1 = __floats2half2_rn(v.z, v.w);
    uint2 o;
    o.x = *(uint32_t*)&h0;
    o.y = *(uint32_t*)&h1;
    ((uint2*)dst)[j] = o;
}

// ---------------- RoPE table: coarse/fine fp64 sincos (4608 instead of 98304) ----
__global__ void rope_base_kernel() {
    int idx = blockIdx.x * blockDim.x + threadIdx.x;
    if (idx >= 96 * 48) return;
    int i = idx % 48;
    double invf = exp(-(double)i / 48.0 * log(10000.0));
    if (idx < 32 * 48) {
        int a = idx / 48;
        double s, c;
        sincos((double)(a * 64) * invf, &s, &c);
        g_cA[idx] = c;
        g_sA[idx] = s;
    } else {
        int k = idx - 32 * 48;
        int r = k / 48;
        double s, c;
        sincos((double)r * invf, &s, &c);
        g_cB[k] = c;
        g_sB[k] = s;
    }
}

// combine: cos(a+b), sin(a+b) via double angle addition (exact to ~1 ulp double)
__global__ void rope_combine_kernel() {
    int idx = blockIdx.x * blockDim.x + threadIdx.x;
    if (idx >= LL * 48) return;
    int i = idx % 48;
    int l = idx / 48;
    int a = l >> 6, r = l & 63;
    double cA = g_cA[a * 48 + i], sA = g_sA[a * 48 + i];
    double cB = g_cB[r * 48 + i], sB = g_sB[r * 48 + i];
    double S = sqrt(17.0 / 12.0);   // sqrt(1 + ln32/ln4096)
    g_cos[idx] = (float)((cA * cB - sA * sB) * S);
    g_sin[idx] = (float)((sA * cB + cA * sB) * S);
}

// ---------------- RoPE + head-major fp16 conversion of q,k,v ----------------
__global__ void rope_conv_kernel() {
    int idx = blockIdx.x * blockDim.x + threadIdx.x;
    const int total = MTOK * NH * 48;
    if (idx >= total) return;
    int i = idx % 48;
    int h = (idx / 48) % NH;
    int t = idx / (48 * NH);
    int b = t >> 11;
    int l = t & (LL - 1);
    float c = g_cos[l * 48 + i];
    float s = g_sin[l * 48 + i];
    const float scale = 0.10206207261596577f;  // 96^-0.5

    const float* qb = g_qkv + (size_t)t * OPSZ + h * HD;
    const float* kb = qb + 3072;
    const float* vb = qb + 6144;

    size_t obase = ((size_t)(b * NH + h) * LL + l) * HD;

    float q0 = qb[i], q1 = qb[i + 48];
    g_qh[obase + i]      = __float2half_rn((q0 * c - q1 * s) * scale);
    g_qh[obase + i + 48] = __float2half_rn((q1 * c + q0 * s) * scale);

    float k0 = kb[i], k1 = kb[i + 48];
    g_kh[obase + i]      = __float2half_rn(k0 * c - k1 * s);
    g_kh[obase + i + 48] = __float2half_rn(k1 * c + k0 * s);

    g_vh[obase + i]      = __float2half_rn(vb[i]);
    g_vh[obase + i + 48] = __float2half_rn(vb[i + 48]);
}

// ---------------- common MMA helpers ----------------
__device__ __forceinline__ void cp16(uint32_t dst, const void* src) {
    asm volatile("cp.async.cg.shared.global [%0], [%1], 16;\n" :: "r"(dst), "l"(src));
}

__device__ __forceinline__ void ldsm4(uint32_t& r0, uint32_t& r1,
                                      uint32_t& r2, uint32_t& r3, uint32_t addr) {
    asm volatile("ldmatrix.sync.aligned.m8n8.x4.shared.b16 {%0,%1,%2,%3}, [%4];"
                 : "=r"(r0), "=r"(r1), "=r"(r2), "=r"(r3) : "r"(addr));
}

__device__ __forceinline__ void ldsm4t(uint32_t& r0, uint32_t& r1,
                                       uint32_t& r2, uint32_t& r3, uint32_t addr) {
    asm volatile("ldmatrix.sync.aligned.m8n8.x4.trans.shared.b16 {%0,%1,%2,%3}, [%4];"
                 : "=r"(r0), "=r"(r1), "=r"(r2), "=r"(r3) : "r"(addr));
}

__device__ __forceinline__ void mma_f16(
    float& d0, float& d1, float& d2, float& d3,
    uint32_t a0, uint32_t a1, uint32_t a2, uint32_t a3,
    uint32_t b0, uint32_t b1)
{
    asm volatile(
        "mma.sync.aligned.m16n8k16.row.col.f32.f16.f16.f32 "
        "{%0,%1,%2,%3}, {%4,%5,%6,%7}, {%8,%9}, {%0,%1,%2,%3};"
        : "+f"(d0), "+f"(d1), "+f"(d2), "+f"(d3)
        : "r"(a0), "r"(a1), "r"(a2), "r"(a3), "r"(b0), "r"(b1));
}

__device__ __forceinline__ uint32_t packh2(float a, float b) {
    __half2 h = __floats2half2_rn(a, b);
    return *(uint32_t*)&h;
}

// ============ fp16 GEMM (wide): BM=128, BN=256, 256 thr — best for large grids ============
#define HPITCH 40
#define ASTG_B (128 * HPITCH * 2)
#define BSTG_B (256 * HPITCH * 2)
#define GEMM_SMEM_BYTES (2 * (ASTG_B + BSTG_B))  // 61440 B

__global__ __launch_bounds__(256) void gemm_f16_nt_kernel(
    const __half* __restrict__ A, const __half* __restrict__ Bm,
    float* __restrict__ C, int M, int N, int K)
{
    extern __shared__ __align__(16) char smc[];
    const uint32_t smem_u32 = (uint32_t)__cvta_generic_to_shared(smc);
    const uint32_t sAbase = smem_u32;
    const uint32_t sBbase = smem_u32 + 2 * ASTG_B;

    const int tid  = threadIdx.x;
    const int w    = tid >> 5;
    const int lane = tid & 31;
    const int wm   = w >> 2;
    const int wn   = w & 3;
    const int g    = lane >> 2;
    const int tk   = lane & 3;
    const int bm   = blockIdx.y * 128;
    const int bn   = blockIdx.x * 256;

    const int aRow = lane & 15;
    const int aK   = (lane >> 4) << 3;
    const int bRow = (lane & 7) + ((lane >> 4) << 3);
    const int bK   = lane & 8;

    const int crowA = tid >> 1;
    const int chA   = (tid & 1) << 4;

    const __half* ApA = A  + (size_t)(bm + crowA) * K + chA;
    const __half* BpB = Bm + (size_t)(bn + tid) * K;

    const uint32_t dstA0 = sAbase + (uint32_t)(crowA * 80 + chA * 2);
    const uint32_t dstB0 = sBbase + (uint32_t)(tid * 80);

    float acc[4][8][4];
#pragma unroll
    for (int mi = 0; mi < 4; mi++)
#pragma unroll
        for (int ni = 0; ni < 8; ni++)
#pragma unroll
            for (int r = 0; r < 4; r++) acc[mi][ni][r] = 0.0f;

    {
        cp16(dstA0,      ApA);
        cp16(dstA0 + 16, ApA + 8);
#pragma unroll
        for (int j = 0; j < 4; j++)
            cp16(dstB0 + j * 16u, BpB + j * 8);
        asm volatile("cp.async.commit_group;\n" ::: "memory");
    }

    int s = 0;
    for (int kb = 0; kb < K; kb += 32) {
        asm volatile("cp.async.wait_group 0;\n" ::: "memory");
        __syncthreads();

        if (kb + 32 < K) {
            const uint32_t so = (uint32_t)(s ^ 1);
            const uint32_t dA = dstA0 + so * ASTG_B;
            const uint32_t dB = dstB0 + so * BSTG_B;
            const __half* a0 = ApA + kb + 32;
            const __half* b0 = BpB + kb + 32;
            cp16(dA,      a0);
            cp16(dA + 16, a0 + 8);
#pragma unroll
            for (int j = 0; j < 4; j++)
                cp16(dB + j * 16u, b0 + j * 8);
            asm volatile("cp.async.commit_group;\n" ::: "memory");
        }

        const uint32_t Ac = sAbase + (uint32_t)s * ASTG_B;
        const uint32_t Bc = sBbase + (uint32_t)s * BSTG_B;

#pragma unroll
        for (int ks = 0; ks < 2; ks++) {
            const int k0 = ks * 16;
            uint32_t af[4][4];
            uint32_t bf[4][4];
#pragma unroll
            for (int mi = 0; mi < 4; mi++) {
                int row = wm * 64 + mi * 16 + aRow;
                ldsm4(af[mi][0], af[mi][1], af[mi][2], af[mi][3],
                      Ac + (uint32_t)((row * HPITCH + k0 + aK) * 2));
            }
#pragma unroll
            for (int n2 = 0; n2 < 4; n2++) {
                int row = wn * 64 + n2 * 16 + bRow;
                ldsm4(bf[n2][0], bf[n2][1], bf[n2][2], bf[n2][3],
                      Bc + (uint32_t)((row * HPITCH + k0 + bK) * 2));
            }
#pragma unroll
            for (int mi = 0; mi < 4; mi++)
#pragma unroll
                for (int n2 = 0; n2 < 4; n2++) {
                    mma_f16(acc[mi][2 * n2][0], acc[mi][2 * n2][1],
                            acc[mi][2 * n2][2], acc[mi][2 * n2][3],
                            af[mi][0], af[mi][1], af[mi][2], af[mi][3],
                            bf[n2][0], bf[n2][1]);
                    mma_f16(acc[mi][2 * n2 + 1][0], acc[mi][2 * n2 + 1][1],
                            acc[mi][2 * n2 + 1][2], acc[mi][2 * n2 + 1][3],
                            af[mi][0], af[mi][1], af[mi][2], af[mi][3],
                            bf[n2][2], bf[n2][3]);
                }
        }
        s ^= 1;
    }

#pragma unroll
    for (int mi = 0; mi < 4; mi++) {
#pragma unroll
        for (int ni = 0; ni < 8; ni++) {
            int row = bm + wm * 64 + mi * 16 + g;
            int col = bn + wn * 64 + ni * 8 + tk * 2;
            *(float2*)(C + (size_t)row * N + col) =
                make_float2(acc[mi][ni][0], acc[mi][ni][1]);
            *(float2*)(C + (size_t)(row + 8) * N + col) =
                make_float2(acc[mi][ni][2], acc[mi][ni][3]);
        }
    }
}

// ============ fp16 GEMM (narrow): BM=128, BN=128, 128 thr — better wave quantization
// for small grids (GEMM2: 768 CTAs = 5.19 waves vs 384 = 2.59). Same 64x64 warp tiles.
#define NBSTG_B (128 * HPITCH * 2)
#define GEMM_N_SMEM_BYTES (2 * (ASTG_B + NBSTG_B))  // 40960 B

__global__ __launch_bounds__(128, 3) void gemm_f16_nt128_kernel(
    const __half* __restrict__ A, const __half* __restrict__ Bm,
    float* __restrict__ C, int M, int N, int K)
{
    extern __shared__ __align__(16) char smc[];
    const uint32_t smem_u32 = (uint32_t)__cvta_generic_to_shared(smc);
    const uint32_t sAbase = smem_u32;
    const uint32_t sBbase = smem_u32 + 2 * ASTG_B;

    const int tid  = threadIdx.x;
    const int w    = tid >> 5;
    const int lane = tid & 31;
    const int wm   = w >> 1;
    const int wn   = w & 1;
    const int g    = lane >> 2;
    const int tk   = lane & 3;
    const int bm   = blockIdx.y * 128;
    const int bn   = blockIdx.x * 128;

    const int aRow = lane & 15;
    const int aK   = (lane >> 4) << 3;
    const int bRow = (lane & 7) + ((lane >> 4) << 3);
    const int bK   = lane & 8;

    const __half* ApA = A  + (size_t)(bm + tid) * K;
    const __half* BpB = Bm + (size_t)(bn + tid) * K;

    const uint32_t dstA0 = sAbase + (uint32_t)(tid * 80);
    const uint32_t dstB0 = sBbase + (uint32_t)(tid * 80);

    float acc[4][8][4];
#pragma unroll
    for (int mi = 0; mi < 4; mi++)
#pragma unroll
        for (int ni = 0; ni < 8; ni++)
#pragma unroll
            for (int r = 0; r < 4; r++) acc[mi][ni][r] = 0.0f;

    {
#pragma unroll
        for (int j = 0; j < 4; j++) {
            cp16(dstA0 + j * 16u, ApA + j * 8);
            cp16(dstB0 + j * 16u, BpB + j * 8);
        }
        asm volatile("cp.async.commit_group;\n" ::: "memory");
    }

    int s = 0;
    for (int kb = 0; kb < K; kb += 32) {
        asm volatile("cp.async.wait_group 0;\n" ::: "memory");
        __syncthreads();

        if (kb + 32 < K) {
            const uint32_t so = (uint32_t)(s ^ 1);
            const uint32_t dA = dstA0 + so * ASTG_B;
            const uint32_t dB = dstB0 + so * NBSTG_B;
            const __half* a0 = ApA + kb + 32;
            const __half* b0 = BpB + kb + 32;
#pragma unroll
            for (int j = 0; j < 4; j++) {
                cp16(dA + j * 16u, a0 + j * 8);
                cp16(dB + j * 16u, b0 + j * 8);
            }
            asm volatile("cp.async.commit_group;\n" ::: "memory");
        }

        const uint32_t Ac = sAbase + (uint32_t)s * ASTG_B;
        const uint32_t Bc = sBbase + (uint32_t)s * NBSTG_B;

#pragma unroll
        for (int ks = 0; ks < 2; ks++) {
            const int k0 = ks * 16;
            uint32_t af[4][4];
            uint32_t bf[4][4];
#pragma unroll
            for (int mi = 0; mi < 4; mi++) {
                int row = wm * 64 + mi * 16 + aRow;
                ldsm4(af[mi][0], af[mi][1], af[mi][2], af[mi][3],
                      Ac + (uint32_t)((row * HPITCH + k0 + aK) * 2));
            }
#pragma unroll
            for (int n2 = 0; n2 < 4; n2++) {
                int row = wn * 64 + n2 * 16 + bRow;
                ldsm4(bf[n2][0], bf[n2][1], bf[n2][2], bf[n2][3],
                      Bc + (uint32_t)((row * HPITCH + k0 + bK) * 2));
            }
#pragma unroll
            for (int mi = 0; mi < 4; mi++)
#pragma unroll
                for (int n2 = 0; n2 < 4; n2++) {
                    mma_f16(acc[mi][2 * n2][0], acc[mi][2 * n2][1],
                            acc[mi][2 * n2][2], acc[mi][2 * n2][3],
                            af[mi][0], af[mi][1], af[mi][2], af[mi][3],
                            bf[n2][0], bf[n2][1]);
                    mma_f16(acc[mi][2 * n2 + 1][0], acc[mi][2 * n2 + 1][1],
                            acc[mi][2 * n2 + 1][2], acc[mi][2 * n2 + 1][3],
                            af[mi][0], af[mi][1], af[mi][2], af[mi][3],
                            bf[n2][2], bf[n2][3]);
                }
        }
        s ^= 1;
    }

#pragma unroll
    for (int mi = 0; mi < 4; mi++) {
#pragma unroll
        for (int ni = 0; ni < 8; ni++) {
            int row = bm + wm * 64 + mi * 16 + g;
            int col = bn + wn * 64 + ni * 8 + tk * 2;
            *(float2*)(C + (size_t)row * N + col) =
                make_float2(acc[mi][ni][0], acc[mi][ni][1]);
            *(float2*)(C + (size_t)(row + 8) * N + col) =
                make_float2(acc[mi][ni][2], acc[mi][ni][3]);
        }
    }
}

// ============ fp16 tensor-core flash attention (3-stage KV ring) ============
#define VP 104
#define QS_BYTES (128 * VP * 2)
#define KV_BYTES (64 * VP * 2)
#define KVSTG    (2 * KV_BYTES)
#define FLASH2_SMEM (QS_BYTES + 3 * KVSTG)  // 106496

__global__ __launch_bounds__(256) void flash_mma_kernel(
    const __half* __restrict__ qh, const __half* __restrict__ kh,
    const __half* __restrict__ vh, __half* __restrict__ out)
{
    extern __shared__ __align__(16) char smc[];
    const uint32_t sb = (uint32_t)__cvta_generic_to_shared(smc);

    const int tid  = threadIdx.x;
    const int w    = tid >> 5;
    const int lane = tid & 31;
    const int qt   = (int)gridDim.x - 1 - (int)blockIdx.x;  // heavy tiles first
    const int bh   = blockIdx.y;
    const int b    = bh >> 5;

    const __half* qbase = qh + ((size_t)bh * LL + qt * 128) * HD;
    const __half* kbase = kh + (size_t)bh * LL * HD;
    const __half* vbase = vh + (size_t)bh * LL * HD;

    const int a15 = lane & 15;
    const int a8  = (lane >> 4) << 3;
    const int bRw = (lane & 7) + ((lane >> 4) << 3);
    const int bK8 = lane & 8;
    const int g   = lane >> 2;
    const int tk  = lane & 3;

    const int qrow = tid >> 1;
    const int qoff = (tid & 1) * 48;
    const int kvrow = (tid & 127) >> 1;
    const int kvoff = (tid & 1) * 48;
    const int isV   = tid >> 7;

    const uint32_t qdst = sb + (uint32_t)((qrow * VP + qoff) * 2);
    const __half* qsrc = qbase + qrow * HD + qoff;

    const int nkb = 2 * qt + 2;

#pragma unroll
    for (int j = 0; j < 6; j++)
        cp16(qdst + j * 16u, qsrc + j * 8);
    {
        const uint32_t kvd = sb + QS_BYTES + (uint32_t)(isV * KV_BYTES)
                           + (uint32_t)((kvrow * VP + kvoff) * 2);
        const __half* src = (isV ? vbase : kbase) + (size_t)kvrow * HD + kvoff;
#pragma unroll
        for (int j = 0; j < 6; j++)
            cp16(kvd + j * 16u, src + j * 8);
        asm volatile("cp.async.commit_group;\n" ::: "memory");
    }
    {
        const uint32_t kvd = sb + QS_BYTES + KVSTG + (uint32_t)(isV * KV_BYTES)
                           + (uint32_t)((kvrow * VP + kvoff) * 2);
        const __half* src = (isV ? vbase : kbase) + (size_t)(64 + kvrow) * HD + kvoff;
#pragma unroll
        for (int j = 0; j < 6; j++)
            cp16(kvd + j * 16u, src + j * 8);
        asm volatile("cp.async.commit_group;\n" ::: "memory");
    }

    float of[12][4];
#pragma unroll
    for (int n = 0; n < 12; n++)
#pragma unroll
        for (int r = 0; r < 4; r++) of[n][r] = 0.0f;
    float m0 = -INFINITY, m1 = -INFINITY, l0 = 0.0f, l1 = 0.0f;
    uint32_t qf[6][4];

    for (int kb = 0; kb < nkb; kb++) {
        if (kb < nkb - 1) asm volatile("cp.async.wait_group 1;\n" ::: "memory");
        else              asm volatile("cp.async.wait_group 0;\n" ::: "memory");
        __syncthreads();

        if (kb + 2 < nkb) {
            const uint32_t st = (uint32_t)((kb + 2) % 3);
            const uint32_t kvd = sb + QS_BYTES + st * KVSTG + (uint32_t)(isV * KV_BYTES)
                               + (uint32_t)((kvrow * VP + kvoff) * 2);
            const __half* src = (isV ? vbase : kbase)
                              + (size_t)((kb + 2) * 64 + kvrow) * HD + kvoff;
#pragma unroll
            for (int j = 0; j < 6; j++)
                cp16(kvd + j * 16u, src + j * 8);
            asm volatile("cp.async.commit_group;\n" ::: "memory");
        }

        if (kb == 0) {
#pragma unroll
            for (int kc = 0; kc < 6; kc++)
                ldsm4(qf[kc][0], qf[kc][1], qf[kc][2], qf[kc][3],
                      sb + (uint32_t)(((w * 16 + a15) * VP + kc * 16 + a8) * 2));
        }

        const uint32_t Kc = sb + QS_BYTES + (uint32_t)(kb % 3) * KVSTG;
        const uint32_t Vc = Kc + KV_BYTES;

        float sf[8][4];
#pragma unroll
        for (int n = 0; n < 8; n++)
#pragma unroll
            for (int r = 0; r < 4; r++) sf[n][r] = 0.0f;

#pragma unroll
        for (int kc = 0; kc < 6; kc++) {
            uint32_t kf[4][4];
#pragma unroll
            for (int n2 = 0; n2 < 4; n2++)
                ldsm4(kf[n2][0], kf[n2][1], kf[n2][2], kf[n2][3],
                      Kc + (uint32_t)(((n2 * 16 + bRw) * VP + kc * 16 + bK8) * 2));
#pragma unroll
            for (int n2 = 0; n2 < 4; n2++) {
                mma_f16(sf[2 * n2][0], sf[2 * n2][1], sf[2 * n2][2], sf[2 * n2][3],
                        qf[kc][0], qf[kc][1], qf[kc][2], qf[kc][3],
                        kf[n2][0], kf[n2][1]);
                mma_f16(sf[2 * n2 + 1][0], sf[2 * n2 + 1][1],
                        sf[2 * n2 + 1][2], sf[2 * n2 + 1][3],
                        qf[kc][0], qf[kc][1], qf[kc][2], qf[kc][3],
                        kf[n2][2], kf[n2][3]);
            }
        }

        if (kb * 64 + 63 > qt * 128 + w * 16) {
            const int r0 = qt * 128 + w * 16 + g;
            const int cb = kb * 64 + tk * 2;
#pragma unroll
            for (int n = 0; n < 8; n++) {
                int c = cb + n * 8;
                if (c     > r0)     sf[n][0] = -1e30f;
                if (c + 1 > r0)     sf[n][1] = -1e30f;
                if (c     > r0 + 8) sf[n][2] = -1e30f;
                if (c + 1 > r0 + 8) sf[n][3] = -1e30f;
            }
        }

        float mx0 = -1e30f, mx1 = -1e30f;
#pragma unroll
        for (int n = 0; n < 8; n++) {
            mx0 = fmaxf(mx0, fmaxf(sf[n][0], sf[n][1]));
            mx1 = fmaxf(mx1, fmaxf(sf[n][2], sf[n][3]));
        }
        mx0 = fmaxf(mx0, __shfl_xor_sync(0xffffffffu, mx0, 1));
        mx0 = fmaxf(mx0, __shfl_xor_sync(0xffffffffu, mx0, 2));
        mx1 = fmaxf(mx1, __shfl_xor_sync(0xffffffffu, mx1, 1));
        mx1 = fmaxf(mx1, __shfl_xor_sync(0xffffffffu, mx1, 2));

        float mn0 = fmaxf(m0, mx0), mn1 = fmaxf(m1, mx1);
        float al0 = __expf(m0 - mn0), al1 = __expf(m1 - mn1);

        uint32_t pf[8][2];
        float ps0 = 0.0f, ps1 = 0.0f;
#pragma unroll
        for (int n = 0; n < 8; n++) {
            float p0 = __expf(sf[n][0] - mn0);
            float p1 = __expf(sf[n][1] - mn0);
            float p2 = __expf(sf[n][2] - mn1);
            float p3 = __expf(sf[n][3] - mn1);
            ps0 += p0 + p1;
            ps1 += p2 + p3;
            pf[n][0] = packh2(p0, p1);
            pf[n][1] = packh2(p2, p3);
        }
        ps0 += __shfl_xor_sync(0xffffffffu, ps0, 1);
        ps0 += __shfl_xor_sync(0xffffffffu, ps0, 2);
        ps1 += __shfl_xor_sync(0xffffffffu, ps1, 1);
        ps1 += __shfl_xor_sync(0xffffffffu, ps1, 2);

        l0 = l0 * al0 + ps0;
        l1 = l1 * al1 + ps1;
        m0 = mn0;
        m1 = mn1;
#pragma unroll
        for (int n = 0; n < 12; n++) {
            of[n][0] *= al0; of[n][1] *= al0;
            of[n][2] *= al1; of[n][3] *= al1;
        }

#pragma unroll
        for (int kk = 0; kk < 4; kk++) {
            uint32_t a0 = pf[2 * kk][0],     a1 = pf[2 * kk][1];
            uint32_t a2 = pf[2 * kk + 1][0], a3 = pf[2 * kk + 1][1];
#pragma unroll
            for (int nv = 0; nv < 6; nv++) {
                uint32_t vf0, vf1, vf2, vf3;
                ldsm4t(vf0, vf1, vf2, vf3,
                       Vc + (uint32_t)(((kk * 16 + a15) * VP + nv * 16 + a8) * 2));
                mma_f16(of[2 * nv][0], of[2 * nv][1], of[2 * nv][2], of[2 * nv][3],
                        a0, a1, a2, a3, vf0, vf1);
                mma_f16(of[2 * nv + 1][0], of[2 * nv + 1][1],
                        of[2 * nv + 1][2], of[2 * nv + 1][3],
                        a0, a1, a2, a3, vf2, vf3);
            }
        }
    }

    const float inv0 = 1.0f / l0;
    const float inv1 = 1.0f / l1;
    const int row0 = qt * 128 + w * 16 + g;
    const int h    = bh & 31;
#pragma unroll
    for (int n = 0; n < 12; n++) {
        int col = h * HD + n * 8 + tk * 2;
        __half2 o0 = __floats2half2_rn(of[n][0] * inv0, of[n][1] * inv0);
        __half2 o1 = __floats2half2_rn(of[n][2] * inv1, of[n][3] * inv1);
        *(__half2*)(out + (size_t)(b * LL + row0) * HIDDEN + col) = o0;
        *(__half2*)(out + (size_t)(b * LL + row0 + 8) * HIDDEN + col) = o1;
    }
}

// ---------------- launch ----------------
extern "C" void kernel_launch(void* const* d_in, const int* in_sizes, int n_in,
                              void* d_out, int out_size)
{
    const float* x    = (const float*)d_in[0];
    const float* Wqkv = (const float*)d_in[1];
    const float* Wo   = (const float*)d_in[2];
    float* out = (float*)d_out;

    float*  qkv;   cudaGetSymbolAddress((void**)&qkv,   g_qkv);
    __half* attnh; cudaGetSymbolAddress((void**)&attnh, g_attnh);
    __half* xh;    cudaGetSymbolAddress((void**)&xh,    g_xh);
    __half* wqh;   cudaGetSymbolAddress((void**)&wqh,   g_wqh);
    __half* woh;   cudaGetSymbolAddress((void**)&woh,   g_woh);
    __half* qh;    cudaGetSymbolAddress((void**)&qh,    g_qh);
    __half* kh;    cudaGetSymbolAddress((void**)&kh,    g_kh);
    __half* vh;    cudaGetSymbolAddress((void**)&vh,    g_vh);

    cudaFuncSetAttribute(gemm_f16_nt_kernel,
                         cudaFuncAttributeMaxDynamicSharedMemorySize, GEMM_SMEM_BYTES);
    cudaFuncSetAttribute(gemm_f16_nt128_kernel,
                         cudaFuncAttributeMaxDynamicSharedMemorySize, GEMM_N_SMEM_BYTES);
    cudaFuncSetAttribute(flash_mma_kernel,
                         cudaFuncAttributeMaxDynamicSharedMemorySize, FLASH2_SMEM);

    // 0) fused fp16 conversion of x, Wqkv, Wo + fast RoPE table
    {
        int ntot = N4X + N4Q + N4O;
        to_half_fused_kernel<<<(ntot + 255) / 256, 256>>>(x, Wqkv, Wo);
        rope_base_kernel<<<(96 * 48 + 255) / 256, 256>>>();
        rope_combine_kernel<<<(LL * 48 + 255) / 256, 256>>>();
    }
    // 1) QKV = x @ Wqkv^T : [4096, 9216]  (wide GEMM, 1152 CTAs: deep waves)
    {
        dim3 grid(OPSZ / 256, MTOK / 128);
        gemm_f16_nt_kernel<<<grid, 256, GEMM_SMEM_BYTES>>>(xh, wqh, qkv, MTOK, OPSZ, HIDDEN);
    }
    // 2) rope/convert to head-major fp16 q,k,v
    {
        int n2 = MTOK * NH * 48;
        rope_conv_kernel<<<(n2 + 255) / 256, 256>>>();
    }
    // 3) tensor-core flash attention -> attnh [4096, 3072] fp16 (3-stage ring)
    {
        dim3 grid(LL / 128, BB * NH);
        flash_mma_kernel<<<grid, 256, FLASH2_SMEM>>>(qh, kh, vh, attnh);
    }
    // 4) out = attn @ Wo^T : [4096, 3072]  (narrow GEMM, 768 CTAs: less tail waste)
    {
        dim3 grid(HIDDEN / 128, MTOK / 128);
        gemm_f16_nt128_kernel<<<grid, 128, GEMM_N_SMEM_BYTES>>>(attnh, woh, out,
                                                                MTOK, HIDDEN, HIDDEN);
    }
}

// round 17
// speedup vs baseline: 1.0475x; 1.0190x over previous
#include <cuda_runtime.h>
#include <cuda_fp16.h>
#include <math.h>
#include <stdint.h>

#define HIDDEN 3072
#define NH     32
#define HD     96
#define OPSZ   9216   // 32*96 + 2*32*96
#define BB     2
#define LL     2048
#define MTOK   4096   // BB*LL

// ---------------- scratch (static device globals; no allocation) ----------------
__device__ __half g_qkvh[(size_t)MTOK * OPSZ];     // [token, 9216] fp16: q | k | v
__device__ __half g_attnh[(size_t)MTOK * HIDDEN];  // fp16 attention output
__device__ __half g_xh [(size_t)MTOK * HIDDEN];    // fp16 x
__device__ __half g_wqh[(size_t)OPSZ * HIDDEN];    // fp16 Wqkv
__device__ __half g_woh[(size_t)HIDDEN * HIDDEN];  // fp16 Wo
__device__ __half g_qh [(size_t)MTOK * HIDDEN];    // head-major fp16 Q (scaled, roped)
__device__ __half g_kh [(size_t)MTOK * HIDDEN];    // head-major fp16 K (roped)
__device__ __half g_vh [(size_t)MTOK * HIDDEN];    // head-major fp16 V
__device__ float  g_cos[LL * 48];
__device__ float  g_sin[LL * 48];
__device__ double g_cA[32 * 48], g_sA[32 * 48];    // coarse phases (l = 64a)
__device__ double g_cB[64 * 48], g_sB[64 * 48];    // fine phases   (l = r)

// ---------------- fused fp32 -> fp16 convert of x, Wqkv, Wo ----------------
#define N4X (MTOK * HIDDEN / 4)
#define N4Q (OPSZ * HIDDEN / 4)
#define N4O (HIDDEN * HIDDEN / 4)

__global__ void to_half_fused_kernel(const float* __restrict__ x,
                                     const float* __restrict__ wq,
                                     const float* __restrict__ wo) {
    int i = blockIdx.x * blockDim.x + threadIdx.x;
    const float* src;
    __half* dst;
    int j;
    if (i < N4X)            { src = x;  dst = g_xh;  j = i; }
    else if (i < N4X + N4Q) { src = wq; dst = g_wqh; j = i - N4X; }
    else if (i < N4X + N4Q + N4O) { src = wo; dst = g_woh; j = i - N4X - N4Q; }
    else return;
    float4 v = ((const float4*)src)[j];
    __half2 h0 = __floats2half2_rn(v.x, v.y);
    __half2 h1 = __floats2half2_rn(v.z, v.w);
    uint2 o;
    o.x = *(uint32_t*)&h0;
    o.y = *(uint32_t*)&h1;
    ((uint2*)dst)[j] = o;
}

// ---------------- RoPE table: coarse/fine fp64 sincos (4608 instead of 98304) ----
__global__ void rope_base_kernel() {
    int idx = blockIdx.x * blockDim.x + threadIdx.x;
    if (idx >= 96 * 48) return;
    int i = idx % 48;
    double invf = exp(-(double)i / 48.0 * log(10000.0));
    if (idx < 32 * 48) {
        int a = idx / 48;
        double s, c;
        sincos((double)(a * 64) * invf, &s, &c);
        g_cA[idx] = c;
        g_sA[idx] = s;
    } else {
        int k = idx - 32 * 48;
        int r = k / 48;
        double s, c;
        sincos((double)r * invf, &s, &c);
        g_cB[k] = c;
        g_sB[k] = s;
    }
}

__global__ void rope_combine_kernel() {
    int idx = blockIdx.x * blockDim.x + threadIdx.x;
    if (idx >= LL * 48) return;
    int i = idx % 48;
    int l = idx / 48;
    int a = l >> 6, r = l & 63;
    double cA = g_cA[a * 48 + i], sA = g_sA[a * 48 + i];
    double cB = g_cB[r * 48 + i], sB = g_sB[r * 48 + i];
    double S = sqrt(17.0 / 12.0);   // sqrt(1 + ln32/ln4096)
    g_cos[idx] = (float)((cA * cB - sA * sB) * S);
    g_sin[idx] = (float)((sA * cB + cA * sB) * S);
}

// ---------------- RoPE + head-major fp16 conversion of q,k,v (fp16 source) --------
__global__ void rope_conv_kernel() {
    int idx = blockIdx.x * blockDim.x + threadIdx.x;
    const int total = MTOK * NH * 48;
    if (idx >= total) return;
    int i = idx % 48;
    int h = (idx / 48) % NH;
    int t = idx / (48 * NH);
    int b = t >> 11;
    int l = t & (LL - 1);
    float c = g_cos[l * 48 + i];
    float s = g_sin[l * 48 + i];
    const float scale = 0.10206207261596577f;  // 96^-0.5

    const __half* qb = g_qkvh + (size_t)t * OPSZ + h * HD;
    const __half* kb = qb + 3072;
    const __half* vb = qb + 6144;

    size_t obase = ((size_t)(b * NH + h) * LL + l) * HD;

    float q0 = __half2float(qb[i]), q1 = __half2float(qb[i + 48]);
    g_qh[obase + i]      = __float2half_rn((q0 * c - q1 * s) * scale);
    g_qh[obase + i + 48] = __float2half_rn((q1 * c + q0 * s) * scale);

    float k0 = __half2float(kb[i]), k1 = __half2float(kb[i + 48]);
    g_kh[obase + i]      = __float2half_rn(k0 * c - k1 * s);
    g_kh[obase + i + 48] = __float2half_rn(k1 * c + k0 * s);

    g_vh[obase + i]      = vb[i];
    g_vh[obase + i + 48] = vb[i + 48];
}

// ---------------- common MMA helpers ----------------
__device__ __forceinline__ void cp16(uint32_t dst, const void* src) {
    asm volatile("cp.async.cg.shared.global [%0], [%1], 16;\n" :: "r"(dst), "l"(src));
}

__device__ __forceinline__ void ldsm4(uint32_t& r0, uint32_t& r1,
                                      uint32_t& r2, uint32_t& r3, uint32_t addr) {
    asm volatile("ldmatrix.sync.aligned.m8n8.x4.shared.b16 {%0,%1,%2,%3}, [%4];"
                 : "=r"(r0), "=r"(r1), "=r"(r2), "=r"(r3) : "r"(addr));
}

__device__ __forceinline__ void ldsm4t(uint32_t& r0, uint32_t& r1,
                                       uint32_t& r2, uint32_t& r3, uint32_t addr) {
    asm volatile("ldmatrix.sync.aligned.m8n8.x4.trans.shared.b16 {%0,%1,%2,%3}, [%4];"
                 : "=r"(r0), "=r"(r1), "=r"(r2), "=r"(r3) : "r"(addr));
}

__device__ __forceinline__ void mma_f16(
    float& d0, float& d1, float& d2, float& d3,
    uint32_t a0, uint32_t a1, uint32_t a2, uint32_t a3,
    uint32_t b0, uint32_t b1)
{
    asm volatile(
        "mma.sync.aligned.m16n8k16.row.col.f32.f16.f16.f32 "
        "{%0,%1,%2,%3}, {%4,%5,%6,%7}, {%8,%9}, {%0,%1,%2,%3};"
        : "+f"(d0), "+f"(d1), "+f"(d2), "+f"(d3)
        : "r"(a0), "r"(a1), "r"(a2), "r"(a3), "r"(b0), "r"(b1));
}

__device__ __forceinline__ uint32_t packh2(float a, float b) {
    __half2 h = __floats2half2_rn(a, b);
    return *(uint32_t*)&h;
}

// ============ fp16 GEMM (wide): BM=128, BN=256, 256 thr, 2-stage cp.async ============
// Template CT: float (fp32 output) or __half (fp16 output).
#define HPITCH 40
#define ASTG_B (128 * HPITCH * 2)
#define BSTG_B (256 * HPITCH * 2)
#define GEMM_SMEM_BYTES (2 * (ASTG_B + BSTG_B))  // 61440 B

template <typename CT>
__global__ __launch_bounds__(256) void gemm_f16_nt_kernel(
    const __half* __restrict__ A, const __half* __restrict__ Bm,
    CT* __restrict__ C, int M, int N, int K)
{
    extern __shared__ __align__(16) char smc[];
    const uint32_t smem_u32 = (uint32_t)__cvta_generic_to_shared(smc);
    const uint32_t sAbase = smem_u32;
    const uint32_t sBbase = smem_u32 + 2 * ASTG_B;

    const int tid  = threadIdx.x;
    const int w    = tid >> 5;
    const int lane = tid & 31;
    const int wm   = w >> 2;
    const int wn   = w & 3;
    const int g    = lane >> 2;
    const int tk   = lane & 3;
    const int bm   = blockIdx.y * 128;
    const int bn   = blockIdx.x * 256;

    const int aRow = lane & 15;
    const int aK   = (lane >> 4) << 3;
    const int bRow = (lane & 7) + ((lane >> 4) << 3);
    const int bK   = lane & 8;

    const int crowA = tid >> 1;
    const int chA   = (tid & 1) << 4;

    const __half* ApA = A  + (size_t)(bm + crowA) * K + chA;
    const __half* BpB = Bm + (size_t)(bn + tid) * K;

    const uint32_t dstA0 = sAbase + (uint32_t)(crowA * 80 + chA * 2);
    const uint32_t dstB0 = sBbase + (uint32_t)(tid * 80);

    float acc[4][8][4];
#pragma unroll
    for (int mi = 0; mi < 4; mi++)
#pragma unroll
        for (int ni = 0; ni < 8; ni++)
#pragma unroll
            for (int r = 0; r < 4; r++) acc[mi][ni][r] = 0.0f;

    {
        cp16(dstA0,      ApA);
        cp16(dstA0 + 16, ApA + 8);
#pragma unroll
        for (int j = 0; j < 4; j++)
            cp16(dstB0 + j * 16u, BpB + j * 8);
        asm volatile("cp.async.commit_group;\n" ::: "memory");
    }

    int s = 0;
    for (int kb = 0; kb < K; kb += 32) {
        asm volatile("cp.async.wait_group 0;\n" ::: "memory");
        __syncthreads();

        if (kb + 32 < K) {
            const uint32_t so = (uint32_t)(s ^ 1);
            const uint32_t dA = dstA0 + so * ASTG_B;
            const uint32_t dB = dstB0 + so * BSTG_B;
            const __half* a0 = ApA + kb + 32;
            const __half* b0 = BpB + kb + 32;
            cp16(dA,      a0);
            cp16(dA + 16, a0 + 8);
#pragma unroll
            for (int j = 0; j < 4; j++)
                cp16(dB + j * 16u, b0 + j * 8);
            asm volatile("cp.async.commit_group;\n" ::: "memory");
        }

        const uint32_t Ac = sAbase + (uint32_t)s * ASTG_B;
        const uint32_t Bc = sBbase + (uint32_t)s * BSTG_B;

#pragma unroll
        for (int ks = 0; ks < 2; ks++) {
            const int k0 = ks * 16;
            uint32_t af[4][4];
            uint32_t bf[4][4];
#pragma unroll
            for (int mi = 0; mi < 4; mi++) {
                int row = wm * 64 + mi * 16 + aRow;
                ldsm4(af[mi][0], af[mi][1], af[mi][2], af[mi][3],
                      Ac + (uint32_t)((row * HPITCH + k0 + aK) * 2));
            }
#pragma unroll
            for (int n2 = 0; n2 < 4; n2++) {
                int row = wn * 64 + n2 * 16 + bRow;
                ldsm4(bf[n2][0], bf[n2][1], bf[n2][2], bf[n2][3],
                      Bc + (uint32_t)((row * HPITCH + k0 + bK) * 2));
            }
#pragma unroll
            for (int mi = 0; mi < 4; mi++)
#pragma unroll
                for (int n2 = 0; n2 < 4; n2++) {
                    mma_f16(acc[mi][2 * n2][0], acc[mi][2 * n2][1],
                            acc[mi][2 * n2][2], acc[mi][2 * n2][3],
                            af[mi][0], af[mi][1], af[mi][2], af[mi][3],
                            bf[n2][0], bf[n2][1]);
                    mma_f16(acc[mi][2 * n2 + 1][0], acc[mi][2 * n2 + 1][1],
                            acc[mi][2 * n2 + 1][2], acc[mi][2 * n2 + 1][3],
                            af[mi][0], af[mi][1], af[mi][2], af[mi][3],
                            bf[n2][2], bf[n2][3]);
                }
        }
        s ^= 1;
    }

#pragma unroll
    for (int mi = 0; mi < 4; mi++) {
#pragma unroll
        for (int ni = 0; ni < 8; ni++) {
            int row = bm + wm * 64 + mi * 16 + g;
            int col = bn + wn * 64 + ni * 8 + tk * 2;
            if (sizeof(CT) == 4) {
                *(float2*)((float*)C + (size_t)row * N + col) =
                    make_float2(acc[mi][ni][0], acc[mi][ni][1]);
                *(float2*)((float*)C + (size_t)(row + 8) * N + col) =
                    make_float2(acc[mi][ni][2], acc[mi][ni][3]);
            } else {
                *(uint32_t*)((__half*)C + (size_t)row * N + col) =
                    packh2(acc[mi][ni][0], acc[mi][ni][1]);
                *(uint32_t*)((__half*)C + (size_t)(row + 8) * N + col) =
                    packh2(acc[mi][ni][2], acc[mi][ni][3]);
            }
        }
    }
}

// ============ fp16 tensor-core flash attention (3-stage KV ring) ============
#define VP 104
#define QS_BYTES (128 * VP * 2)
#define KV_BYTES (64 * VP * 2)
#define KVSTG    (2 * KV_BYTES)
#define FLASH2_SMEM (QS_BYTES + 3 * KVSTG)  // 106496

__global__ __launch_bounds__(256) void flash_mma_kernel(
    const __half* __restrict__ qh, const __half* __restrict__ kh,
    const __half* __restrict__ vh, __half* __restrict__ out)
{
    extern __shared__ __align__(16) char smc[];
    const uint32_t sb = (uint32_t)__cvta_generic_to_shared(smc);

    const int tid  = threadIdx.x;
    const int w    = tid >> 5;
    const int lane = tid & 31;
    const int qt   = (int)gridDim.x - 1 - (int)blockIdx.x;  // heavy tiles first
    const int bh   = blockIdx.y;
    const int b    = bh >> 5;

    const __half* qbase = qh + ((size_t)bh * LL + qt * 128) * HD;
    const __half* kbase = kh + (size_t)bh * LL * HD;
    const __half* vbase = vh + (size_t)bh * LL * HD;

    const int a15 = lane & 15;
    const int a8  = (lane >> 4) << 3;
    const int bRw = (lane & 7) + ((lane >> 4) << 3);
    const int bK8 = lane & 8;
    const int g   = lane >> 2;
    const int tk  = lane & 3;

    const int qrow = tid >> 1;
    const int qoff = (tid & 1) * 48;
    const int kvrow = (tid & 127) >> 1;
    const int kvoff = (tid & 1) * 48;
    const int isV   = tid >> 7;

    const uint32_t qdst = sb + (uint32_t)((qrow * VP + qoff) * 2);
    const __half* qsrc = qbase + qrow * HD + qoff;

    const int nkb = 2 * qt + 2;

#pragma unroll
    for (int j = 0; j < 6; j++)
        cp16(qdst + j * 16u, qsrc + j * 8);
    {
        const uint32_t kvd = sb + QS_BYTES + (uint32_t)(isV * KV_BYTES)
                           + (uint32_t)((kvrow * VP + kvoff) * 2);
        const __half* src = (isV ? vbase : kbase) + (size_t)kvrow * HD + kvoff;
#pragma unroll
        for (int j = 0; j < 6; j++)
            cp16(kvd + j * 16u, src + j * 8);
        asm volatile("cp.async.commit_group;\n" ::: "memory");
    }
    {
        const uint32_t kvd = sb + QS_BYTES + KVSTG + (uint32_t)(isV * KV_BYTES)
                           + (uint32_t)((kvrow * VP + kvoff) * 2);
        const __half* src = (isV ? vbase : kbase) + (size_t)(64 + kvrow) * HD + kvoff;
#pragma unroll
        for (int j = 0; j < 6; j++)
            cp16(kvd + j * 16u, src + j * 8);
        asm volatile("cp.async.commit_group;\n" ::: "memory");
    }

    float of[12][4];
#pragma unroll
    for (int n = 0; n < 12; n++)
#pragma unroll
        for (int r = 0; r < 4; r++) of[n][r] = 0.0f;
    float m0 = -INFINITY, m1 = -INFINITY, l0 = 0.0f, l1 = 0.0f;
    uint32_t qf[6][4];

    for (int kb = 0; kb < nkb; kb++) {
        if (kb < nkb - 1) asm volatile("cp.async.wait_group 1;\n" ::: "memory");
        else              asm volatile("cp.async.wait_group 0;\n" ::: "memory");
        __syncthreads();

        if (kb + 2 < nkb) {
            const uint32_t st = (uint32_t)((kb + 2) % 3);
            const uint32_t kvd = sb + QS_BYTES + st * KVSTG + (uint32_t)(isV * KV_BYTES)
                               + (uint32_t)((kvrow * VP + kvoff) * 2);
            const __half* src = (isV ? vbase : kbase)
                              + (size_t)((kb + 2) * 64 + kvrow) * HD + kvoff;
#pragma unroll
            for (int j = 0; j < 6; j++)
                cp16(kvd + j * 16u, src + j * 8);
            asm volatile("cp.async.commit_group;\n" ::: "memory");
        }

        if (kb == 0) {
#pragma unroll
            for (int kc = 0; kc < 6; kc++)
                ldsm4(qf[kc][0], qf[kc][1], qf[kc][2], qf[kc][3],
                      sb + (uint32_t)(((w * 16 + a15) * VP + kc * 16 + a8) * 2));
        }

        const uint32_t Kc = sb + QS_BYTES + (uint32_t)(kb % 3) * KVSTG;
        const uint32_t Vc = Kc + KV_BYTES;

        float sf[8][4];
#pragma unroll
        for (int n = 0; n < 8; n++)
#pragma unroll
            for (int r = 0; r < 4; r++) sf[n][r] = 0.0f;

#pragma unroll
        for (int kc = 0; kc < 6; kc++) {
            uint32_t kf[4][4];
#pragma unroll
            for (int n2 = 0; n2 < 4; n2++)
                ldsm4(kf[n2][0], kf[n2][1], kf[n2][2], kf[n2][3],
                      Kc + (uint32_t)(((n2 * 16 + bRw) * VP + kc * 16 + bK8) * 2));
#pragma unroll
            for (int n2 = 0; n2 < 4; n2++) {
                mma_f16(sf[2 * n2][0], sf[2 * n2][1], sf[2 * n2][2], sf[2 * n2][3],
                        qf[kc][0], qf[kc][1], qf[kc][2], qf[kc][3],
                        kf[n2][0], kf[n2][1]);
                mma_f16(sf[2 * n2 + 1][0], sf[2 * n2 + 1][1],
                        sf[2 * n2 + 1][2], sf[2 * n2 + 1][3],
                        qf[kc][0], qf[kc][1], qf[kc][2], qf[kc][3],
                        kf[n2][2], kf[n2][3]);
            }
        }

        if (kb * 64 + 63 > qt * 128 + w * 16) {
            const int r0 = qt * 128 + w * 16 + g;
            const int cb = kb * 64 + tk * 2;
#pragma unroll
            for (int n = 0; n < 8; n++) {
                int c = cb + n * 8;
                if (c     > r0)     sf[n][0] = -1e30f;
                if (c + 1 > r0)     sf[n][1] = -1e30f;
                if (c     > r0 + 8) sf[n][2] = -1e30f;
                if (c + 1 > r0 + 8) sf[n][3] = -1e30f;
            }
        }

        float mx0 = -1e30f, mx1 = -1e30f;
#pragma unroll
        for (int n = 0; n < 8; n++) {
            mx0 = fmaxf(mx0, fmaxf(sf[n][0], sf[n][1]));
            mx1 = fmaxf(mx1, fmaxf(sf[n][2], sf[n][3]));
        }
        mx0 = fmaxf(mx0, __shfl_xor_sync(0xffffffffu, mx0, 1));
        mx0 = fmaxf(mx0, __shfl_xor_sync(0xffffffffu, mx0, 2));
        mx1 = fmaxf(mx1, __shfl_xor_sync(0xffffffffu, mx1, 1));
        mx1 = fmaxf(mx1, __shfl_xor_sync(0xffffffffu, mx1, 2));

        float mn0 = fmaxf(m0, mx0), mn1 = fmaxf(m1, mx1);
        float al0 = __expf(m0 - mn0), al1 = __expf(m1 - mn1);

        uint32_t pf[8][2];
        float ps0 = 0.0f, ps1 = 0.0f;
#pragma unroll
        for (int n = 0; n < 8; n++) {
            float p0 = __expf(sf[n][0] - mn0);
            float p1 = __expf(sf[n][1] - mn0);
            float p2 = __expf(sf[n][2] - mn1);
            float p3 = __expf(sf[n][3] - mn1);
            ps0 += p0 + p1;
            ps1 += p2 + p3;
            pf[n][0] = packh2(p0, p1);
            pf[n][1] = packh2(p2, p3);
        }
        ps0 += __shfl_xor_sync(0xffffffffu, ps0, 1);
        ps0 += __shfl_xor_sync(0xffffffffu, ps0, 2);
        ps1 += __shfl_xor_sync(0xffffffffu, ps1, 1);
        ps1 += __shfl_xor_sync(0xffffffffu, ps1, 2);

        l0 = l0 * al0 + ps0;
        l1 = l1 * al1 + ps1;
        m0 = mn0;
        m1 = mn1;
#pragma unroll
        for (int n = 0; n < 12; n++) {
            of[n][0] *= al0; of[n][1] *= al0;
            of[n][2] *= al1; of[n][3] *= al1;
        }

#pragma unroll
        for (int kk = 0; kk < 4; kk++) {
            uint32_t a0 = pf[2 * kk][0],     a1 = pf[2 * kk][1];
            uint32_t a2 = pf[2 * kk + 1][0], a3 = pf[2 * kk + 1][1];
#pragma unroll
            for (int nv = 0; nv < 6; nv++) {
                uint32_t vf0, vf1, vf2, vf3;
                ldsm4t(vf0, vf1, vf2, vf3,
                       Vc + (uint32_t)(((kk * 16 + a15) * VP + nv * 16 + a8) * 2));
                mma_f16(of[2 * nv][0], of[2 * nv][1], of[2 * nv][2], of[2 * nv][3],
                        a0, a1, a2, a3, vf0, vf1);
                mma_f16(of[2 * nv + 1][0], of[2 * nv + 1][1],
                        of[2 * nv + 1][2], of[2 * nv + 1][3],
                        a0, a1, a2, a3, vf2, vf3);
            }
        }
    }

    const float inv0 = 1.0f / l0;
    const float inv1 = 1.0f / l1;
    const int row0 = qt * 128 + w * 16 + g;
    const int h    = bh & 31;
#pragma unroll
    for (int n = 0; n < 12; n++) {
        int col = h * HD + n * 8 + tk * 2;
        __half2 o0 = __floats2half2_rn(of[n][0] * inv0, of[n][1] * inv0);
        __half2 o1 = __floats2half2_rn(of[n][2] * inv1, of[n][3] * inv1);
        *(__half2*)(out + (size_t)(b * LL + row0) * HIDDEN + col) = o0;
        *(__half2*)(out + (size_t)(b * LL + row0 + 8) * HIDDEN + col) = o1;
    }
}

// ---------------- launch ----------------
extern "C" void kernel_launch(void* const* d_in, const int* in_sizes, int n_in,
                              void* d_out, int out_size)
{
    const float* x    = (const float*)d_in[0];
    const float* Wqkv = (const float*)d_in[1];
    const float* Wo   = (const float*)d_in[2];
    float* out = (float*)d_out;

    __half* qkvh;  cudaGetSymbolAddress((void**)&qkvh,  g_qkvh);
    __half* attnh; cudaGetSymbolAddress((void**)&attnh, g_attnh);
    __half* xh;    cudaGetSymbolAddress((void**)&xh,    g_xh);
    __half* wqh;   cudaGetSymbolAddress((void**)&wqh,   g_wqh);
    __half* woh;   cudaGetSymbolAddress((void**)&woh,   g_woh);
    __half* qh;    cudaGetSymbolAddress((void**)&qh,    g_qh);
    __half* kh;    cudaGetSymbolAddress((void**)&kh,    g_kh);
    __half* vh;    cudaGetSymbolAddress((void**)&vh,    g_vh);

    cudaFuncSetAttribute(gemm_f16_nt_kernel<float>,
                         cudaFuncAttributeMaxDynamicSharedMemorySize, GEMM_SMEM_BYTES);
    cudaFuncSetAttribute(gemm_f16_nt_kernel<__half>,
                         cudaFuncAttributeMaxDynamicSharedMemorySize, GEMM_SMEM_BYTES);
    cudaFuncSetAttribute(flash_mma_kernel,
                         cudaFuncAttributeMaxDynamicSharedMemorySize, FLASH2_SMEM);

    // 0) fused fp16 conversion of x, Wqkv, Wo + fast RoPE table
    {
        int ntot = N4X + N4Q + N4O;
        to_half_fused_kernel<<<(ntot + 255) / 256, 256>>>(x, Wqkv, Wo);
        rope_base_kernel<<<(96 * 48 + 255) / 256, 256>>>();
        rope_combine_kernel<<<(LL * 48 + 255) / 256, 256>>>();
    }
    // 1) QKV = x @ Wqkv^T : [4096, 9216]  (fp16 output — halves qkv traffic)
    {
        dim3 grid(OPSZ / 256, MTOK / 128);
        gemm_f16_nt_kernel<__half><<<grid, 256, GEMM_SMEM_BYTES>>>(
            xh, wqh, qkvh, MTOK, OPSZ, HIDDEN);
    }
    // 2) rope/convert to head-major fp16 q,k,v
    {
        int n2 = MTOK * NH * 48;
        rope_conv_kernel<<<(n2 + 255) / 256, 256>>>();
    }
    // 3) tensor-core flash attention -> attnh [4096, 3072] fp16 (3-stage ring)
    {
        dim3 grid(LL / 128, BB * NH);
        flash_mma_kernel<<<grid, 256, FLASH2_SMEM>>>(qh, kh, vh, attnh);
    }
    // 4) out = attn @ Wo^T : [4096, 3072]  (wide GEMM — best measured config)
    {
        dim3 grid(HIDDEN / 256, MTOK / 128);
        gemm_f16_nt_kernel<float><<<grid, 256, GEMM_SMEM_BYTES>>>(
            attnh, woh, out, MTOK, HIDDEN, HIDDEN);
    }
}